// round 6
// baseline (speedup 1.0000x reference)
#include <cuda_runtime.h>

#define G 512
#define NVERT (G * G)

// sign(normal_z) == sign(e0x*e2y - e0y*e2x) for the single winning face per
// vertex (last-write-wins scatter; angle weight >= 0 in every branch). Only
// the x,y planes of X are needed. Output = (tnz >= 0) ? 0 : 1, broadcast to
// all 3 channels.
//
// 4 columns per thread (float4). Left-neighbor column values come from the
// previous lane via shfl_up (only lane 0 per warp issues 2 predicated scalar
// loads). 256-thread blocks cover 2 output rows -> 1024 CTAs, 8192 warps.
__global__ void __launch_bounds__(256) vis_mask_kernel(const float* __restrict__ X,
                                                       float* __restrict__ out) {
    const int tx   = threadIdx.x & 127;       // column group within row
    const int ty   = threadIdx.x >> 7;        // 0..1: which row of the pair
    const int lane = threadIdx.x & 31;
    const int c0   = tx << 2;                 // 128 * 4 = 512 columns
    const int r    = (blockIdx.x << 1) + ty;
    const int b    = blockIdx.y;

    const int rA = (r >= 1) ? (r - 1) : 0;
    const int rB = (r >= 1) ? r : 1;
    const bool row0 = (r == 0);

    const float* Xx = X + (size_t)b * 3 * NVERT;
    const float* Xy = Xx + NVERT;

    // lane-0 scalar left-neighbor loads, issued first so they overlap the
    // vector loads.
    float xBl_s = 0.f, yBl_s = 0.f, xAl_s = 0.f, yAl_s = 0.f;
    if (lane == 0 && c0 > 0) {
        xBl_s = Xx[rB * G + c0 - 1];
        yBl_s = Xy[rB * G + c0 - 1];
        if (row0) {
            xAl_s = Xx[rA * G + c0 - 1];
            yAl_s = Xy[rA * G + c0 - 1];
        }
    }

    const float4 xA4 = *(const float4*)(Xx + rA * G + c0);
    const float4 yA4 = *(const float4*)(Xy + rA * G + c0);
    const float4 xB4 = *(const float4*)(Xx + rB * G + c0);
    const float4 yB4 = *(const float4*)(Xy + rB * G + c0);

    // Left neighbors: previous lane's .w component (cols c0-4..c0-1).
    float xBl = __shfl_up_sync(0xffffffffu, xB4.w, 1);
    float yBl = __shfl_up_sync(0xffffffffu, yB4.w, 1);
    if (lane == 0) { xBl = xBl_s; yBl = yBl_s; }

    float xAl = 0.f, yAl = 0.f;
    if (row0) {
        xAl = __shfl_up_sync(0xffffffffu, xA4.w, 1);
        yAl = __shfl_up_sync(0xffffffffu, yA4.w, 1);
        if (lane == 0) { xAl = xAl_s; yAl = yAl_s; }
    }

    const float xa[5] = {xAl, xA4.x, xA4.y, xA4.z, xA4.w};
    const float ya[5] = {yAl, yA4.x, yA4.y, yA4.z, yA4.w};
    const float xb[5] = {xBl, xB4.x, xB4.y, xB4.z, xB4.w};
    const float yb[5] = {yBl, yB4.x, yB4.y, yB4.z, yB4.w};

    float o[4];
#pragma unroll
    for (int k = 0; k < 4; k++) {
        float e0x, e0y, e2x, e2y;
        if (!row0) {
            if (k == 0 && c0 == 0) {
                // c==0: v0=(r-1,1), v1=(r,0), v2=(r,1)
                e0x = xb[1] - xa[2];  e0y = yb[1] - ya[2];
                e2x = xb[1] - xb[2];  e2y = yb[1] - yb[2];
            } else {
                // v0=(r-1,c), v1=(r,c-1), v2=(r,c)
                e0x = xb[k] - xa[k + 1];  e0y = yb[k] - ya[k + 1];
                e2x = xb[k] - xb[k + 1];  e2y = yb[k] - yb[k + 1];
            }
        } else {
            if (k == 0 && c0 == 0) {
                // (0,0): v0=(0,0), v1=(1,0), v2=(0,1)
                e0x = xb[1] - xa[1];  e0y = yb[1] - ya[1];
                e2x = xb[1] - xa[2];  e2y = yb[1] - ya[2];
            } else {
                // r==0: v0=(0,c-1), v1=(1,c-1), v2=(0,c)
                e0x = xb[k] - xa[k];      e0y = yb[k] - ya[k];
                e2x = xb[k] - xa[k + 1];  e2y = yb[k] - ya[k + 1];
            }
        }
        o[k] = (e0x * e2y - e0y * e2x >= 0.0f) ? 0.0f : 1.0f;
    }

    const float4 ov = make_float4(o[0], o[1], o[2], o[3]);
    float* ob = out + (size_t)b * 3 * NVERT + (size_t)r * G + c0;
    *(float4*)(ob)             = ov;
    *(float4*)(ob + NVERT)     = ov;
    *(float4*)(ob + 2 * NVERT) = ov;
}

extern "C" void kernel_launch(void* const* d_in, const int* in_sizes, int n_in,
                              void* d_out, int out_size) {
    const float* X = (const float*)d_in[0];   // (4, 3, 512*512) float32
    // d_in[1] = faces (int32) — implicit in the grid structure, unused.
    float* out = (float*)d_out;               // (4, 3, 512, 512) float32

    dim3 block(256, 1, 1);
    dim3 grid(G / 2, 4, 1);   // 256 row-pairs x 4 batches = 1024 blocks
    vis_mask_kernel<<<grid, block>>>(X, out);
}

// round 7
// speedup vs baseline: 1.4057x; 1.4057x over previous
#include <cuda_runtime.h>

#define G 512
#define NVERT (G * G)

// sign(normal_z) == sign(e0x*e2y - e0y*e2x) for the single winning face per
// vertex (last-write-wins scatter; angle weight >= 0 in every branch). Only
// the x,y planes of X are needed. Output = (tnz >= 0) ? 0 : 1 on all 3
// channels.
//
// R1 structure (4 cols/thread, float4 loads, scalar left-neighbor loads that
// hit L1), but 64-thread CTAs: 4096 CTAs x 2 warps for smoother ramp/spread.
__global__ void __launch_bounds__(64) vis_mask_kernel(const float* __restrict__ X,
                                                      float* __restrict__ out) {
    const int c0 = (blockIdx.x * 64 + threadIdx.x) << 2;  // 2 blocks x 64 thr x 4 = 512 cols
    const int r  = blockIdx.y;
    const int b  = blockIdx.z;

    const float* Xx = X + (size_t)b * 3 * NVERT;
    const float* Xy = Xx + NVERT;

    const int rA = (r >= 1) ? (r - 1) : 0;
    const int rB = (r >= 1) ? r : 1;
    const bool row0 = (r == 0);

    const float4 xA = *(const float4*)(Xx + rA * G + c0);
    const float4 yA = *(const float4*)(Xy + rA * G + c0);
    const float4 xB = *(const float4*)(Xx + rB * G + c0);
    const float4 yB = *(const float4*)(Xy + rB * G + c0);

    // Left-neighbor scalars at column c0-1 (L1 hits on neighbor-thread lines).
    float xAm = 0.f, yAm = 0.f, xBm = 0.f, yBm = 0.f;
    if (c0 > 0) {
        xBm = Xx[rB * G + c0 - 1];
        yBm = Xy[rB * G + c0 - 1];
        if (row0) {
            xAm = Xx[rA * G + c0 - 1];
            yAm = Xy[rA * G + c0 - 1];
        }
    }

    const float xa[5] = {xAm, xA.x, xA.y, xA.z, xA.w};
    const float ya[5] = {yAm, yA.x, yA.y, yA.z, yA.w};
    const float xb[5] = {xBm, xB.x, xB.y, xB.z, xB.w};
    const float yb[5] = {yBm, yB.x, yB.y, yB.z, yB.w};

    float o[4];
#pragma unroll
    for (int k = 0; k < 4; k++) {
        const int c = c0 + k;
        float e0x, e0y, e2x, e2y;
        if (!row0) {
            if (c >= 1) {
                // v0=(r-1,c), v1=(r,c-1), v2=(r,c)
                e0x = xb[k] - xa[k + 1];  e0y = yb[k] - ya[k + 1];
                e2x = xb[k] - xb[k + 1];  e2y = yb[k] - yb[k + 1];
            } else {
                // c==0: v0=(r-1,1), v1=(r,0), v2=(r,1)
                e0x = xb[1] - xa[2];  e0y = yb[1] - ya[2];
                e2x = xb[1] - xb[2];  e2y = yb[1] - yb[2];
            }
        } else {
            if (c >= 1) {
                // r==0: v0=(0,c-1), v1=(1,c-1), v2=(0,c)
                e0x = xb[k] - xa[k];      e0y = yb[k] - ya[k];
                e2x = xb[k] - xa[k + 1];  e2y = yb[k] - ya[k + 1];
            } else {
                // (0,0): v0=(0,0), v1=(1,0), v2=(0,1)
                e0x = xb[1] - xa[1];  e0y = yb[1] - ya[1];
                e2x = xb[1] - xa[2];  e2y = yb[1] - ya[2];
            }
        }
        o[k] = (e0x * e2y - e0y * e2x >= 0.0f) ? 0.0f : 1.0f;
    }

    const float4 ov = make_float4(o[0], o[1], o[2], o[3]);
    float* ob = out + (size_t)b * 3 * NVERT + (size_t)r * G + c0;
    *(float4*)(ob)             = ov;
    *(float4*)(ob + NVERT)     = ov;
    *(float4*)(ob + 2 * NVERT) = ov;
}

extern "C" void kernel_launch(void* const* d_in, const int* in_sizes, int n_in,
                              void* d_out, int out_size) {
    const float* X = (const float*)d_in[0];   // (4, 3, 512*512) float32
    // d_in[1] = faces (int32) — implicit in the grid structure, unused.
    float* out = (float*)d_out;               // (4, 3, 512, 512) float32

    dim3 block(64, 1, 1);
    dim3 grid(2, G, 4);   // 2 col-halves x 512 rows x 4 batches = 4096 CTAs
    vis_mask_kernel<<<grid, block>>>(X, out);
}